// round 12
// baseline (speedup 1.0000x reference)
#include <cuda_runtime.h>
#include <cstdint>

#define B 8
#define H 12
#define S 4096
#define D 64
#define BH (B*H)        // 96
#define TOPK 128

// Scratch (device globals; no allocation allowed)
__device__ unsigned g_key[BH * S];        // order-preserving uint importance keys
__device__ int      g_idx[BH * TOPK];     // selected indices per head
__device__ unsigned g_selmask[BH * 128];  // selected-row bitmap per head

__device__ __forceinline__ unsigned key_of(float f) {
    unsigned u = __float_as_uint(f);
    return (u & 0x80000000u) ? ~u : (u | 0x80000000u);
}

__device__ __forceinline__ float to_tf32(float x) {
    unsigned u;
    asm("cvt.rna.tf32.f32 %0, %1;" : "=r"(u) : "f"(x));
    return __uint_as_float(u);
}

__device__ __forceinline__ void mma_tf32(float c[4],
                                         unsigned a0, unsigned a1, unsigned a2, unsigned a3,
                                         unsigned b0, unsigned b1) {
    asm volatile(
        "mma.sync.aligned.m16n8k8.row.col.f32.tf32.tf32.f32 "
        "{%0,%1,%2,%3}, {%4,%5,%6,%7}, {%8,%9}, {%0,%1,%2,%3};"
        : "+f"(c[0]), "+f"(c[1]), "+f"(c[2]), "+f"(c[3])
        : "r"(a0), "r"(a1), "r"(a2), "r"(a3), "r"(b0), "r"(b1));
}

// ---------------------------------------------------------------------------
// Kernel 1: importance keys (wide grid, full HBM read bandwidth).
// ---------------------------------------------------------------------------
__global__ __launch_bounds__(256)
void imp_kernel(const float* __restrict__ q) {
    int warp = (blockIdx.x * blockDim.x + threadIdx.x) >> 5;
    int lane = threadIdx.x & 31;
    int sub  = lane >> 3;
    int cl   = lane & 7;
    int r0   = warp * 16 + sub;

    float4 a[4], b[4];
    #pragma unroll
    for (int t = 0; t < 4; t++) {
        const float4* p = reinterpret_cast<const float4*>(q + (size_t)(r0 + 4 * t) * D) + cl;
        a[t] = p[0];
        b[t] = p[8];
    }

    float s[4], s2[4];
    #pragma unroll
    for (int t = 0; t < 4; t++) {
        s[t]  = (a[t].x + a[t].y) + (a[t].z + a[t].w) +
                (b[t].x + b[t].y) + (b[t].z + b[t].w);
        s2[t] = a[t].x * a[t].x + a[t].y * a[t].y + a[t].z * a[t].z + a[t].w * a[t].w +
                b[t].x * b[t].x + b[t].y * b[t].y + b[t].z * b[t].z + b[t].w * b[t].w;
    }
    #pragma unroll
    for (int o = 1; o < 8; o <<= 1)
        #pragma unroll
        for (int t = 0; t < 4; t++) {
            s[t]  += __shfl_xor_sync(0xFFFFFFFFu, s[t],  o);
            s2[t] += __shfl_xor_sync(0xFFFFFFFFu, s2[t], o);
        }

    if (cl == 0) {
        #pragma unroll
        for (int t = 0; t < 4; t++) {
            float mean = s[t] * (1.0f / 64.0f);
            float var  = (s2[t] - s[t] * mean) * (1.0f / 63.0f);
            g_key[r0 + 4 * t] = key_of(mean + sqrtf(fmaxf(var, 0.0f)));
        }
    }
}

// ---------------------------------------------------------------------------
// Kernel 2: exact top-128 per head (4-pass MSB radix select) -> g_idx + mask.
// ---------------------------------------------------------------------------
__global__ __launch_bounds__(256)
void topk_kernel() {
    __shared__ unsigned keys[S];
    __shared__ int hist[256];
    __shared__ unsigned mask[128];
    __shared__ int s_digit, s_need, s_n;

    const int bh  = blockIdx.x;
    const int tid = threadIdx.x;
    const unsigned* krow = g_key + (size_t)bh * S;

    for (int i = tid; i < S; i += 256) keys[i] = krow[i];
    if (tid < 128) mask[tid] = 0u;

    unsigned prefix = 0u;
    int need = TOPK;

    #pragma unroll
    for (int shift = 24; shift >= 0; shift -= 8) {
        hist[tid] = 0;
        __syncthreads();

        unsigned pmask = (shift == 24) ? 0u : (0xFFFFFFFFu << (shift + 8));
        for (int i = tid; i < S; i += 256) {
            unsigned u = keys[i];
            if ((u & pmask) == prefix)
                atomicAdd(&hist[(u >> shift) & 255u], 1);
        }
        __syncthreads();

        if (tid < 32) {
            int base = 255 - tid * 8;
            int h[8];
            int gs = 0;
            #pragma unroll
            for (int j = 0; j < 8; j++) { h[j] = hist[base - j]; gs += h[j]; }
            int pre = gs;
            #pragma unroll
            for (int o = 1; o < 32; o <<= 1) {
                int t = __shfl_up_sync(0xFFFFFFFFu, pre, o);
                if (tid >= o) pre += t;
            }
            int excl = pre - gs;
            if (excl < need && need <= pre) {
                int cum = excl, j = 0;
                #pragma unroll
                for (; j < 8; j++) { cum += h[j]; if (cum >= need) break; }
                s_digit = base - j;
                s_need  = need - (cum - h[j]);
            }
        }
        __syncthreads();
        prefix |= ((unsigned)s_digit) << shift;
        need = s_need;
        __syncthreads();
    }

    const unsigned T = prefix;

    if (tid == 0) s_n = 0;
    __syncthreads();
    for (int i = tid; i < S; i += 256) {
        if (keys[i] > T) {
            int p = atomicAdd(&s_n, 1);
            g_idx[bh * TOPK + p] = i;
        }
    }
    __syncthreads();
    for (int i = tid; i < S; i += 256) {
        if (keys[i] == T) {
            int p = atomicAdd(&s_n, 1);
            if (p < TOPK) g_idx[bh * TOPK + p] = i;
        }
    }
    __syncthreads();
    if (tid < TOPK) {
        int i = g_idx[bh * TOPK + tid];
        atomicOr(&mask[i >> 5], 1u << (i & 31));
    }
    __syncthreads();
    if (tid < 128) g_selmask[bh * 128 + tid] = mask[tid];
}

// ---------------------------------------------------------------------------
// Kernel 3: zero all UNSELECTED output rows. WIDE grid (1536 CTAs).
// Runs on the side stream, overlapping attn (disjoint output rows).
// ---------------------------------------------------------------------------
__global__ __launch_bounds__(256)
void zero_kernel(float* __restrict__ out) {
    __shared__ unsigned mask[8];
    const int bh  = blockIdx.x >> 4;
    const int seg = blockIdx.x & 15;          // 256 rows per segment
    const int tid = threadIdx.x;
    if (tid < 8) mask[tid] = g_selmask[bh * 128 + seg * 8 + tid];
    __syncthreads();

    float4* obase = reinterpret_cast<float4*>(out + (size_t)bh * S * D) + (seg * 256) * 16;
    const float4 z = make_float4(0.f, 0.f, 0.f, 0.f);

    #pragma unroll 4
    for (int i = tid; i < 256 * 16; i += 256) {
        int r = i >> 4;
        if (!(mask[r >> 5] & (1u << (r & 31))))
            obase[i] = z;
    }
}

// ---------------------------------------------------------------------------
// Kernel 4: tf32 tensor-core attention. 96 CTAs x 1024 threads (32 warps),
// warp tiles 16x32 (GEMM1) / 16x16 (GEMM2).
// ---------------------------------------------------------------------------
#define PITCH  68
#define PPITCH 132

__global__ __launch_bounds__(1024, 1)
void attn_kernel(const float* __restrict__ q, const float* __restrict__ k,
                 const float* __restrict__ v, float* __restrict__ out) {
    extern __shared__ float sm[];
    float* qs = sm;                          // 128 x PITCH (dead after GEMM1)
    float* ks = qs + 128 * PITCH;            // 128 x PITCH (dead after GEMM1)
    float* vs = ks + 128 * PITCH;            // 128 x PITCH
    float* ps = sm;                          // 128 x PPITCH alias over qs+ks
    __shared__ int sidx[TOPK];

    const int bh   = blockIdx.x;
    const int tid  = threadIdx.x;
    const int lane = tid & 31;
    const int w    = tid >> 5;           // 32 warps

    if (tid < TOPK) sidx[tid] = g_idx[bh * TOPK + tid];
    __syncthreads();

    const size_t base = (size_t)bh * S * D;

    // Gather q,k,v (tf32-rounded): 8 threads/row, 2 float4 each
    {
        int r = tid >> 3, p = tid & 7;
        size_t goff = base + (size_t)sidx[r] * D + p * 8;
        const float4* gq = reinterpret_cast<const float4*>(q + goff);
        const float4* gk = reinterpret_cast<const float4*>(k + goff);
        const float4* gv = reinterpret_cast<const float4*>(v + goff);
        float* dq = qs + r * PITCH + p * 8;
        float* dk = ks + r * PITCH + p * 8;
        float* dv = vs + r * PITCH + p * 8;
        #pragma unroll
        for (int i = 0; i < 2; i++) {
            float4 q4 = gq[i], k4 = gk[i], v4 = gv[i];
            q4.x = to_tf32(q4.x); q4.y = to_tf32(q4.y);
            q4.z = to_tf32(q4.z); q4.w = to_tf32(q4.w);
            k4.x = to_tf32(k4.x); k4.y = to_tf32(k4.y);
            k4.z = to_tf32(k4.z); k4.w = to_tf32(k4.w);
            v4.x = to_tf32(v4.x); v4.y = to_tf32(v4.y);
            v4.z = to_tf32(v4.z); v4.w = to_tf32(v4.w);
            reinterpret_cast<float4*>(dq)[i] = q4;
            reinterpret_cast<float4*>(dk)[i] = k4;
            reinterpret_cast<float4*>(dv)[i] = v4;
        }
    }
    __syncthreads();

    const int wm = w & 7;                // 8 m-groups of 16 rows
    const int wn = w >> 3;               // 4 n-groups
    const int m0 = wm * 16;
    const int lr = lane >> 2;
    const int lc = lane & 3;

    // GEMM1: warp tile 16x32 (4 nb), 8 k-steps
    float c1[4][4];
    #pragma unroll
    for (int nb = 0; nb < 4; nb++)
        #pragma unroll
        for (int j = 0; j < 4; j++) c1[nb][j] = 0.0f;

    #pragma unroll
    for (int kk = 0; kk < 8; kk++) {
        const int k0 = kk * 8;
        unsigned a0 = __float_as_uint(qs[(m0 + lr)     * PITCH + k0 + lc]);
        unsigned a1 = __float_as_uint(qs[(m0 + lr + 8) * PITCH + k0 + lc]);
        unsigned a2 = __float_as_uint(qs[(m0 + lr)     * PITCH + k0 + lc + 4]);
        unsigned a3 = __float_as_uint(qs[(m0 + lr + 8) * PITCH + k0 + lc + 4]);
        #pragma unroll
        for (int nb = 0; nb < 4; nb++) {
            const int n0 = wn * 32 + nb * 8;
            unsigned b0 = __float_as_uint(ks[(n0 + lr) * PITCH + k0 + lc]);
            unsigned b1 = __float_as_uint(ks[(n0 + lr) * PITCH + k0 + lc + 4]);
            mma_tf32(c1[nb], a0, a1, a2, a3, b0, b1);
        }
    }
    __syncthreads();   // all warps done reading qs/ks before ps overwrite

    #pragma unroll
    for (int nb = 0; nb < 4; nb++) {
        const int col = wn * 32 + nb * 8 + lc * 2;
        ps[(m0 + lr)     * PPITCH + col]     = c1[nb][0] * 0.125f;
        ps[(m0 + lr)     * PPITCH + col + 1] = c1[nb][1] * 0.125f;
        ps[(m0 + lr + 8) * PPITCH + col]     = c1[nb][2] * 0.125f;
        ps[(m0 + lr + 8) * PPITCH + col + 1] = c1[nb][3] * 0.125f;
    }
    __syncthreads();

    // Row softmax (32 warps x 4 rows), tf32 probs
    #pragma unroll
    for (int rr = 0; rr < 4; rr++) {
        int r = w * 4 + rr;
        float* row = ps + r * PPITCH;
        float x[4];
        float mx = -1e30f;
        #pragma unroll
        for (int c = 0; c < 4; c++) { x[c] = row[lane + 32 * c]; mx = fmaxf(mx, x[c]); }
        #pragma unroll
        for (int o = 16; o; o >>= 1) mx = fmaxf(mx, __shfl_xor_sync(0xFFFFFFFFu, mx, o));
        float ssum = 0.0f;
        #pragma unroll
        for (int c = 0; c < 4; c++) { x[c] = __expf(x[c] - mx); ssum += x[c]; }
        #pragma unroll
        for (int o = 16; o; o >>= 1) ssum += __shfl_xor_sync(0xFFFFFFFFu, ssum, o);
        float inv = 1.0f / ssum;
        #pragma unroll
        for (int c = 0; c < 4; c++) row[lane + 32 * c] = to_tf32(x[c] * inv);
    }
    __syncthreads();

    // GEMM2: warp tile 16x16 (2 nb), 16 k-steps + scatter
    float c2[2][4];
    #pragma unroll
    for (int nb = 0; nb < 2; nb++)
        #pragma unroll
        for (int j = 0; j < 4; j++) c2[nb][j] = 0.0f;

    #pragma unroll
    for (int kk = 0; kk < 16; kk++) {
        const int k0 = kk * 8;
        unsigned a0 = __float_as_uint(ps[(m0 + lr)     * PPITCH + k0 + lc]);
        unsigned a1 = __float_as_uint(ps[(m0 + lr + 8) * PPITCH + k0 + lc]);
        unsigned a2 = __float_as_uint(ps[(m0 + lr)     * PPITCH + k0 + lc + 4]);
        unsigned a3 = __float_as_uint(ps[(m0 + lr + 8) * PPITCH + k0 + lc + 4]);
        #pragma unroll
        for (int nb = 0; nb < 2; nb++) {
            const int n0 = wn * 16 + nb * 8;
            unsigned b0 = __float_as_uint(vs[(k0 + lc)     * PITCH + n0 + lr]);
            unsigned b1 = __float_as_uint(vs[(k0 + lc + 4) * PITCH + n0 + lr]);
            mma_tf32(c2[nb], a0, a1, a2, a3, b0, b1);
        }
    }

    {
        int r0g = sidx[m0 + lr];
        int r1g = sidx[m0 + lr + 8];
        float* o0 = out + base + (size_t)r0g * D;
        float* o1 = out + base + (size_t)r1g * D;
        #pragma unroll
        for (int nb = 0; nb < 2; nb++) {
            const int d0 = wn * 16 + nb * 8 + lc * 2;
            *reinterpret_cast<float2*>(o0 + d0) = make_float2(c2[nb][0], c2[nb][1]);
            *reinterpret_cast<float2*>(o1 + d0) = make_float2(c2[nb][2], c2[nb][3]);
        }
    }
}

// ---------------------------------------------------------------------------
extern "C" void kernel_launch(void* const* d_in, const int* in_sizes, int n_in,
                              void* d_out, int out_size) {
    const float* q = (const float*)d_in[0];
    const float* k = (const float*)d_in[1];
    const float* v = (const float*)d_in[2];
    float* out = (float*)d_out;

    static cudaStream_t s1 = nullptr;
    static cudaEvent_t  e0 = nullptr, e1 = nullptr;
    if (s1 == nullptr) {
        cudaStreamCreateWithFlags(&s1, cudaStreamNonBlocking);
        cudaEventCreateWithFlags(&e0, cudaEventDisableTiming);
        cudaEventCreateWithFlags(&e1, cudaEventDisableTiming);
    }

    const int attn_smem = (3 * 128 * PITCH) * (int)sizeof(float);
    cudaFuncSetAttribute(attn_kernel, cudaFuncAttributeMaxDynamicSharedMemorySize,
                         attn_smem);

    // 1) importance keys (wide grid, full read bandwidth)
    imp_kernel<<<(BH * S) / 128, 256>>>(q);

    // 2) exact top-128 per head + bitmap
    topk_kernel<<<BH, 256>>>();

    // Fork: wide zero on side stream (write-pipe bound) while attn
    // (tensor/smem bound) computes+writes selected rows on the main stream.
    cudaEventRecord(e0, 0);
    cudaStreamWaitEvent(s1, e0, 0);
    zero_kernel<<<BH * 16, 256, 0, s1>>>(out);
    cudaEventRecord(e1, s1);

    // 3) tf32 tensor-core attention (96 CTAs x 1024 threads)
    attn_kernel<<<BH, 1024, attn_smem>>>(q, k, v, out);

    // Join
    cudaStreamWaitEvent(0, e1, 0);
}

// round 13
// speedup vs baseline: 1.1339x; 1.1339x over previous
#include <cuda_runtime.h>
#include <cstdint>

#define B 8
#define H 12
#define S 4096
#define D 64
#define BH (B*H)        // 96
#define TOPK 128

// Scratch (device globals; no allocation allowed)
__device__ unsigned g_key[BH * S];   // order-preserving uint importance keys

__device__ __forceinline__ unsigned key_of(float f) {
    unsigned u = __float_as_uint(f);
    return (u & 0x80000000u) ? ~u : (u | 0x80000000u);
}

__device__ __forceinline__ float to_tf32(float x) {
    unsigned u;
    asm("cvt.rna.tf32.f32 %0, %1;" : "=r"(u) : "f"(x));
    return __uint_as_float(u);
}

__device__ __forceinline__ void mma_tf32(float c[4],
                                         unsigned a0, unsigned a1, unsigned a2, unsigned a3,
                                         unsigned b0, unsigned b1) {
    asm volatile(
        "mma.sync.aligned.m16n8k8.row.col.f32.tf32.tf32.f32 "
        "{%0,%1,%2,%3}, {%4,%5,%6,%7}, {%8,%9}, {%0,%1,%2,%3};"
        : "+f"(c[0]), "+f"(c[1]), "+f"(c[2]), "+f"(c[3])
        : "r"(a0), "r"(a1), "r"(a2), "r"(a3), "r"(b0), "r"(b1));
}

// ---------------------------------------------------------------------------
// Kernel 1 (FUSED): importance keys + zero the FULL output slab.
// Wide grid (3072 CTAs). Read stream (q) and write stream (out) share HBM at
// mixed bandwidth; the zero-writes are fire-and-forget. attn later overwrites
// the selected rows (graph-serialized).
// ---------------------------------------------------------------------------
__global__ __launch_bounds__(256)
void imp_zero_kernel(const float* __restrict__ q, float* __restrict__ out) {
    const int tid  = threadIdx.x;
    int warp = (blockIdx.x * blockDim.x + tid) >> 5;
    int lane = tid & 31;
    int sub  = lane >> 3;
    int cl   = lane & 7;
    int r0   = warp * 16 + sub;

    // ---- zero 128 output rows for this block (coalesced STG.128) --------
    {
        float4* obase = reinterpret_cast<float4*>(out) + (size_t)blockIdx.x * 128 * 16;
        const float4 z = make_float4(0.f, 0.f, 0.f, 0.f);
        #pragma unroll
        for (int i = 0; i < 8; i++)
            obase[tid + 256 * i] = z;
    }

    // ---- importance keys --------------------------------------------------
    float4 a[4], b[4];
    #pragma unroll
    for (int t = 0; t < 4; t++) {
        const float4* p = reinterpret_cast<const float4*>(q + (size_t)(r0 + 4 * t) * D) + cl;
        a[t] = p[0];
        b[t] = p[8];
    }

    float s[4], s2[4];
    #pragma unroll
    for (int t = 0; t < 4; t++) {
        s[t]  = (a[t].x + a[t].y) + (a[t].z + a[t].w) +
                (b[t].x + b[t].y) + (b[t].z + b[t].w);
        s2[t] = a[t].x * a[t].x + a[t].y * a[t].y + a[t].z * a[t].z + a[t].w * a[t].w +
                b[t].x * b[t].x + b[t].y * b[t].y + b[t].z * b[t].z + b[t].w * b[t].w;
    }
    #pragma unroll
    for (int o = 1; o < 8; o <<= 1)
        #pragma unroll
        for (int t = 0; t < 4; t++) {
            s[t]  += __shfl_xor_sync(0xFFFFFFFFu, s[t],  o);
            s2[t] += __shfl_xor_sync(0xFFFFFFFFu, s2[t], o);
        }

    if (cl == 0) {
        #pragma unroll
        for (int t = 0; t < 4; t++) {
            float mean = s[t] * (1.0f / 64.0f);
            float var  = (s2[t] - s[t] * mean) * (1.0f / 63.0f);
            g_key[r0 + 4 * t] = key_of(mean + sqrtf(fmaxf(var, 0.0f)));
        }
    }
}

// ---------------------------------------------------------------------------
// Kernel 2 (FUSED): top-128 radix select + tf32 attention + scatter.
// One CTA per head: 96 CTAs x 1024 threads (32 warps). (R11 structure.)
// ---------------------------------------------------------------------------
#define PITCH  68
#define PPITCH 132

__global__ __launch_bounds__(1024, 1)
void fused_kernel(const float* __restrict__ q, const float* __restrict__ k,
                  const float* __restrict__ v, float* __restrict__ out) {
    extern __shared__ float sm[];
    unsigned* keys = reinterpret_cast<unsigned*>(sm);   // 16 KB, dead after select
    float* qs = sm;                          // 128 x PITCH (dead after GEMM1)
    float* ks = qs + 128 * PITCH;            // 128 x PITCH (dead after GEMM1)
    float* vs = ks + 128 * PITCH;            // 128 x PITCH
    float* ps = sm;                          // 128 x PPITCH alias over qs+ks

    __shared__ int sidx[TOPK];
    __shared__ int hist[256];
    __shared__ int s_digit, s_need, s_n;

    const int bh   = blockIdx.x;
    const int tid  = threadIdx.x;
    const int lane = tid & 31;
    const int w    = tid >> 5;           // 32 warps

    // ---- Phase A: load keys, radix-select the 128th-largest --------------
    const unsigned* krow = g_key + (size_t)bh * S;
    for (int i = tid; i < S; i += 1024) keys[i] = krow[i];

    unsigned prefix = 0u;
    int need = TOPK;

    #pragma unroll
    for (int shift = 24; shift >= 0; shift -= 8) {
        if (tid < 256) hist[tid] = 0;
        __syncthreads();

        unsigned pmask = (shift == 24) ? 0u : (0xFFFFFFFFu << (shift + 8));
        for (int i = tid; i < S; i += 1024) {
            unsigned u = keys[i];
            if ((u & pmask) == prefix)
                atomicAdd(&hist[(u >> shift) & 255u], 1);
        }
        __syncthreads();

        if (tid < 32) {
            int base = 255 - tid * 8;
            int h[8];
            int gs = 0;
            #pragma unroll
            for (int j = 0; j < 8; j++) { h[j] = hist[base - j]; gs += h[j]; }
            int pre = gs;
            #pragma unroll
            for (int o = 1; o < 32; o <<= 1) {
                int t = __shfl_up_sync(0xFFFFFFFFu, pre, o);
                if (tid >= o) pre += t;
            }
            int excl = pre - gs;
            if (excl < need && need <= pre) {
                int cum = excl, j = 0;
                #pragma unroll
                for (; j < 8; j++) { cum += h[j]; if (cum >= need) break; }
                s_digit = base - j;
                s_need  = need - (cum - h[j]);
            }
        }
        __syncthreads();
        prefix |= ((unsigned)s_digit) << shift;
        need = s_need;
        __syncthreads();
    }

    const unsigned T = prefix;

    if (tid == 0) s_n = 0;
    __syncthreads();
    for (int i = tid; i < S; i += 1024) {
        if (keys[i] > T) {
            int p = atomicAdd(&s_n, 1);
            sidx[p] = i;
        }
    }
    __syncthreads();
    for (int i = tid; i < S; i += 1024) {
        if (keys[i] == T) {
            int p = atomicAdd(&s_n, 1);
            if (p < TOPK) sidx[p] = i;
        }
    }
    __syncthreads();

    const size_t base = (size_t)bh * S * D;

    // ---- Phase B: gather q,k,v (tf32-rounded) into smem ------------------
    {
        int r = tid >> 3, p = tid & 7;
        size_t goff = base + (size_t)sidx[r] * D + p * 8;
        const float4* gq = reinterpret_cast<const float4*>(q + goff);
        const float4* gk = reinterpret_cast<const float4*>(k + goff);
        const float4* gv = reinterpret_cast<const float4*>(v + goff);
        float* dq = qs + r * PITCH + p * 8;
        float* dk = ks + r * PITCH + p * 8;
        float* dv = vs + r * PITCH + p * 8;
        #pragma unroll
        for (int i = 0; i < 2; i++) {
            float4 q4 = gq[i], k4 = gk[i], v4 = gv[i];
            q4.x = to_tf32(q4.x); q4.y = to_tf32(q4.y);
            q4.z = to_tf32(q4.z); q4.w = to_tf32(q4.w);
            k4.x = to_tf32(k4.x); k4.y = to_tf32(k4.y);
            k4.z = to_tf32(k4.z); k4.w = to_tf32(k4.w);
            v4.x = to_tf32(v4.x); v4.y = to_tf32(v4.y);
            v4.z = to_tf32(v4.z); v4.w = to_tf32(v4.w);
            reinterpret_cast<float4*>(dq)[i] = q4;
            reinterpret_cast<float4*>(dk)[i] = k4;
            reinterpret_cast<float4*>(dv)[i] = v4;
        }
    }
    __syncthreads();

    const int wm = w & 7;                // 8 m-groups of 16 rows
    const int wn = w >> 3;               // 4 n-groups
    const int m0 = wm * 16;
    const int lr = lane >> 2;
    const int lc = lane & 3;

    // ---- Phase C: GEMM1, warp tile 16x32 (4 nb), 8 k-steps ---------------
    float c1[4][4];
    #pragma unroll
    for (int nb = 0; nb < 4; nb++)
        #pragma unroll
        for (int j = 0; j < 4; j++) c1[nb][j] = 0.0f;

    #pragma unroll
    for (int kk = 0; kk < 8; kk++) {
        const int k0 = kk * 8;
        unsigned a0 = __float_as_uint(qs[(m0 + lr)     * PITCH + k0 + lc]);
        unsigned a1 = __float_as_uint(qs[(m0 + lr + 8) * PITCH + k0 + lc]);
        unsigned a2 = __float_as_uint(qs[(m0 + lr)     * PITCH + k0 + lc + 4]);
        unsigned a3 = __float_as_uint(qs[(m0 + lr + 8) * PITCH + k0 + lc + 4]);
        #pragma unroll
        for (int nb = 0; nb < 4; nb++) {
            const int n0 = wn * 32 + nb * 8;
            unsigned b0 = __float_as_uint(ks[(n0 + lr) * PITCH + k0 + lc]);
            unsigned b1 = __float_as_uint(ks[(n0 + lr) * PITCH + k0 + lc + 4]);
            mma_tf32(c1[nb], a0, a1, a2, a3, b0, b1);
        }
    }
    __syncthreads();   // all warps done reading qs/ks before ps overwrite

    #pragma unroll
    for (int nb = 0; nb < 4; nb++) {
        const int col = wn * 32 + nb * 8 + lc * 2;
        ps[(m0 + lr)     * PPITCH + col]     = c1[nb][0] * 0.125f;
        ps[(m0 + lr)     * PPITCH + col + 1] = c1[nb][1] * 0.125f;
        ps[(m0 + lr + 8) * PPITCH + col]     = c1[nb][2] * 0.125f;
        ps[(m0 + lr + 8) * PPITCH + col + 1] = c1[nb][3] * 0.125f;
    }
    __syncthreads();

    // ---- Phase D: row softmax (32 warps x 4 rows), tf32 probs ------------
    #pragma unroll
    for (int rr = 0; rr < 4; rr++) {
        int r = w * 4 + rr;
        float* row = ps + r * PPITCH;
        float x[4];
        float mx = -1e30f;
        #pragma unroll
        for (int c = 0; c < 4; c++) { x[c] = row[lane + 32 * c]; mx = fmaxf(mx, x[c]); }
        #pragma unroll
        for (int o = 16; o; o >>= 1) mx = fmaxf(mx, __shfl_xor_sync(0xFFFFFFFFu, mx, o));
        float ssum = 0.0f;
        #pragma unroll
        for (int c = 0; c < 4; c++) { x[c] = __expf(x[c] - mx); ssum += x[c]; }
        #pragma unroll
        for (int o = 16; o; o >>= 1) ssum += __shfl_xor_sync(0xFFFFFFFFu, ssum, o);
        float inv = 1.0f / ssum;
        #pragma unroll
        for (int c = 0; c < 4; c++) row[lane + 32 * c] = to_tf32(x[c] * inv);
    }
    __syncthreads();

    // ---- Phase E: GEMM2, warp tile 16x16 (2 nb), 16 k-steps + scatter ----
    float c2[2][4];
    #pragma unroll
    for (int nb = 0; nb < 2; nb++)
        #pragma unroll
        for (int j = 0; j < 4; j++) c2[nb][j] = 0.0f;

    #pragma unroll
    for (int kk = 0; kk < 16; kk++) {
        const int k0 = kk * 8;
        unsigned a0 = __float_as_uint(ps[(m0 + lr)     * PPITCH + k0 + lc]);
        unsigned a1 = __float_as_uint(ps[(m0 + lr + 8) * PPITCH + k0 + lc]);
        unsigned a2 = __float_as_uint(ps[(m0 + lr)     * PPITCH + k0 + lc + 4]);
        unsigned a3 = __float_as_uint(ps[(m0 + lr + 8) * PPITCH + k0 + lc + 4]);
        #pragma unroll
        for (int nb = 0; nb < 2; nb++) {
            const int n0 = wn * 16 + nb * 8;
            unsigned b0 = __float_as_uint(vs[(k0 + lc)     * PITCH + n0 + lr]);
            unsigned b1 = __float_as_uint(vs[(k0 + lc + 4) * PITCH + n0 + lr]);
            mma_tf32(c2[nb], a0, a1, a2, a3, b0, b1);
        }
    }

    {
        int r0g = sidx[m0 + lr];
        int r1g = sidx[m0 + lr + 8];
        float* o0 = out + base + (size_t)r0g * D;
        float* o1 = out + base + (size_t)r1g * D;
        #pragma unroll
        for (int nb = 0; nb < 2; nb++) {
            const int d0 = wn * 16 + nb * 8 + lc * 2;
            *reinterpret_cast<float2*>(o0 + d0) = make_float2(c2[nb][0], c2[nb][1]);
            *reinterpret_cast<float2*>(o1 + d0) = make_float2(c2[nb][2], c2[nb][3]);
        }
    }
}

// ---------------------------------------------------------------------------
extern "C" void kernel_launch(void* const* d_in, const int* in_sizes, int n_in,
                              void* d_out, int out_size) {
    const float* q = (const float*)d_in[0];
    const float* k = (const float*)d_in[1];
    const float* v = (const float*)d_in[2];
    float* out = (float*)d_out;

    const int fused_smem = (3 * 128 * PITCH) * (int)sizeof(float);
    cudaFuncSetAttribute(fused_kernel, cudaFuncAttributeMaxDynamicSharedMemorySize,
                         fused_smem);

    // 1) importance keys + full output zero (wide grid, mixed R/W bandwidth)
    imp_zero_kernel<<<(BH * S) / 128, 256>>>(q, out);

    // 2) fused select + tensor-core attention; overwrites selected rows
    fused_kernel<<<BH, 1024, fused_smem>>>(q, k, v, out);
}

// round 14
// speedup vs baseline: 1.1585x; 1.0217x over previous
#include <cuda_runtime.h>
#include <cstdint>

#define B 8
#define H 12
#define S 4096
#define D 64
#define BH (B*H)        // 96
#define TOPK 128

// Scratch (device globals; no allocation allowed)
__device__ unsigned g_key[BH * S];       // order-preserving uint importance keys
__device__ int      g_hist[BH * 256];    // per-head top-byte histograms

__device__ __forceinline__ unsigned key_of(float f) {
    unsigned u = __float_as_uint(f);
    return (u & 0x80000000u) ? ~u : (u | 0x80000000u);
}

__device__ __forceinline__ float to_tf32(float x) {
    unsigned u;
    asm("cvt.rna.tf32.f32 %0, %1;" : "=r"(u) : "f"(x));
    return __uint_as_float(u);
}

__device__ __forceinline__ void mma_tf32(float c[4],
                                         unsigned a0, unsigned a1, unsigned a2, unsigned a3,
                                         unsigned b0, unsigned b1) {
    asm volatile(
        "mma.sync.aligned.m16n8k8.row.col.f32.tf32.tf32.f32 "
        "{%0,%1,%2,%3}, {%4,%5,%6,%7}, {%8,%9}, {%0,%1,%2,%3};"
        : "+f"(c[0]), "+f"(c[1]), "+f"(c[2]), "+f"(c[3])
        : "r"(a0), "r"(a1), "r"(a2), "r"(a3), "r"(b0), "r"(b1));
}

// ---------------------------------------------------------------------------
// Kernel 1 (FUSED): importance keys + full-output zero + per-head top-byte
// histogram. Wide grid (3072 CTAs; 32 CTAs per head, 128 rows per CTA).
// ---------------------------------------------------------------------------
__global__ __launch_bounds__(256)
void imp_zero_kernel(const float* __restrict__ q, float* __restrict__ out) {
    __shared__ int hist[256];
    const int tid  = threadIdx.x;
    int warp = (blockIdx.x * blockDim.x + tid) >> 5;
    int lane = tid & 31;
    int sub  = lane >> 3;
    int cl   = lane & 7;
    int r0   = warp * 16 + sub;

    hist[tid] = 0;

    // ---- zero 128 output rows for this block (coalesced STG.128) --------
    {
        float4* obase = reinterpret_cast<float4*>(out) + (size_t)blockIdx.x * 128 * 16;
        const float4 z = make_float4(0.f, 0.f, 0.f, 0.f);
        #pragma unroll
        for (int i = 0; i < 8; i++)
            obase[tid + 256 * i] = z;
    }
    __syncthreads();   // hist zeroed

    // ---- importance keys ---------------------------------------------------
    float4 a[4], b[4];
    #pragma unroll
    for (int t = 0; t < 4; t++) {
        const float4* p = reinterpret_cast<const float4*>(q + (size_t)(r0 + 4 * t) * D) + cl;
        a[t] = p[0];
        b[t] = p[8];
    }

    float s[4], s2[4];
    #pragma unroll
    for (int t = 0; t < 4; t++) {
        s[t]  = (a[t].x + a[t].y) + (a[t].z + a[t].w) +
                (b[t].x + b[t].y) + (b[t].z + b[t].w);
        s2[t] = a[t].x * a[t].x + a[t].y * a[t].y + a[t].z * a[t].z + a[t].w * a[t].w +
                b[t].x * b[t].x + b[t].y * b[t].y + b[t].z * b[t].z + b[t].w * b[t].w;
    }
    #pragma unroll
    for (int o = 1; o < 8; o <<= 1)
        #pragma unroll
        for (int t = 0; t < 4; t++) {
            s[t]  += __shfl_xor_sync(0xFFFFFFFFu, s[t],  o);
            s2[t] += __shfl_xor_sync(0xFFFFFFFFu, s2[t], o);
        }

    if (cl == 0) {
        #pragma unroll
        for (int t = 0; t < 4; t++) {
            float mean = s[t] * (1.0f / 64.0f);
            float var  = (s2[t] - s[t] * mean) * (1.0f / 63.0f);
            unsigned key = key_of(mean + sqrtf(fmaxf(var, 0.0f)));
            g_key[r0 + 4 * t] = key;
            atomicAdd(&hist[key >> 24], 1);
        }
    }
    __syncthreads();
    // merge CTA hist into per-head global hist (fire-and-forget REDG)
    atomicAdd(&g_hist[(blockIdx.x >> 5) * 256 + tid], hist[tid]);
}

// ---------------------------------------------------------------------------
// Kernel 2 (FUSED): top-128 radix select (pass 1 from g_hist) + tf32 attention.
// One CTA per head: 96 CTAs x 1024 threads.
// Permuted-k smem layout: logical k stored at ((k&3)<<1)|(k>>2) within each
// 8-block -> mma fragment pairs (k, k+4) are adjacent -> LDS.64 loads.
// ---------------------------------------------------------------------------
#define PITCH  72    // floats per q/k/v row; %32 == 8 -> conflict-free LDS.64
#define PPITCH 136   // floats per ps row;    %32 == 8

__global__ __launch_bounds__(1024, 1)
void fused_kernel(const float* __restrict__ q, const float* __restrict__ k,
                  const float* __restrict__ v, float* __restrict__ out) {
    extern __shared__ float sm[];
    unsigned* keys = reinterpret_cast<unsigned*>(sm);   // 16 KB, dead after select
    float* qs = sm;                          // 128 x PITCH (dead after GEMM1)
    float* ks = qs + 128 * PITCH;            // 128 x PITCH (dead after GEMM1)
    float* vs = ks + 128 * PITCH;            // 128 x PITCH (unpermuted)
    float* ps = sm;                          // 128 x PPITCH alias over qs+ks

    __shared__ int sidx[TOPK];
    __shared__ int hist[256];
    __shared__ int s_digit, s_need, s_n;

    const int bh   = blockIdx.x;
    const int tid  = threadIdx.x;
    const int lane = tid & 31;
    const int w    = tid >> 5;           // 32 warps

    // ---- Phase A: radix select; pass 1 comes precomputed from g_hist ------
    const unsigned* krow = g_key + (size_t)bh * S;
    for (int i = tid; i < S; i += 1024) keys[i] = krow[i];
    if (tid < 256) hist[tid] = g_hist[bh * 256 + tid];
    __syncthreads();

    unsigned prefix = 0u;
    int need = TOPK;

    // digit-find for pass 1 (shift=24) on the precomputed hist
    {
        if (tid < 32) {
            int base = 255 - tid * 8;
            int h[8];
            int gs = 0;
            #pragma unroll
            for (int j = 0; j < 8; j++) { h[j] = hist[base - j]; gs += h[j]; }
            int pre = gs;
            #pragma unroll
            for (int o = 1; o < 32; o <<= 1) {
                int t = __shfl_up_sync(0xFFFFFFFFu, pre, o);
                if (tid >= o) pre += t;
            }
            int excl = pre - gs;
            if (excl < need && need <= pre) {
                int cum = excl, j = 0;
                #pragma unroll
                for (; j < 8; j++) { cum += h[j]; if (cum >= need) break; }
                s_digit = base - j;
                s_need  = need - (cum - h[j]);
            }
        }
        __syncthreads();
        prefix = ((unsigned)s_digit) << 24;
        need = s_need;
        __syncthreads();
    }

    // passes 2..4 (shift = 16, 8, 0)
    #pragma unroll
    for (int shift = 16; shift >= 0; shift -= 8) {
        if (tid < 256) hist[tid] = 0;
        __syncthreads();

        unsigned pmask = 0xFFFFFFFFu << (shift + 8);
        for (int i = tid; i < S; i += 1024) {
            unsigned u = keys[i];
            if ((u & pmask) == prefix)
                atomicAdd(&hist[(u >> shift) & 255u], 1);
        }
        __syncthreads();

        if (tid < 32) {
            int base = 255 - tid * 8;
            int h[8];
            int gs = 0;
            #pragma unroll
            for (int j = 0; j < 8; j++) { h[j] = hist[base - j]; gs += h[j]; }
            int pre = gs;
            #pragma unroll
            for (int o = 1; o < 32; o <<= 1) {
                int t = __shfl_up_sync(0xFFFFFFFFu, pre, o);
                if (tid >= o) pre += t;
            }
            int excl = pre - gs;
            if (excl < need && need <= pre) {
                int cum = excl, j = 0;
                #pragma unroll
                for (; j < 8; j++) { cum += h[j]; if (cum >= need) break; }
                s_digit = base - j;
                s_need  = need - (cum - h[j]);
            }
        }
        __syncthreads();
        prefix |= ((unsigned)s_digit) << shift;
        need = s_need;
        __syncthreads();
    }

    const unsigned T = prefix;

    if (tid == 0) s_n = 0;
    __syncthreads();
    for (int i = tid; i < S; i += 1024) {
        if (keys[i] > T) {
            int p = atomicAdd(&s_n, 1);
            sidx[p] = i;
        }
    }
    __syncthreads();
    for (int i = tid; i < S; i += 1024) {
        if (keys[i] == T) {
            int p = atomicAdd(&s_n, 1);
            if (p < TOPK) sidx[p] = i;
        }
    }
    __syncthreads();

    const size_t base = (size_t)bh * S * D;

    // ---- Phase B: gather. q,k stored with permuted-k layout; v plain. ----
    {
        int r = tid >> 3, p8 = tid & 7;            // p8 = which 8-wide k-block
        size_t goff = base + (size_t)sidx[r] * D + p8 * 8;
        const float4* gq = reinterpret_cast<const float4*>(q + goff);
        const float4* gk = reinterpret_cast<const float4*>(k + goff);
        const float4* gv = reinterpret_cast<const float4*>(v + goff);

        float4 q0 = gq[0], q1 = gq[1];
        float4 k0v = gk[0], k1v = gk[1];
        float4 v0 = gv[0], v1 = gv[1];

        q0.x = to_tf32(q0.x); q0.y = to_tf32(q0.y); q0.z = to_tf32(q0.z); q0.w = to_tf32(q0.w);
        q1.x = to_tf32(q1.x); q1.y = to_tf32(q1.y); q1.z = to_tf32(q1.z); q1.w = to_tf32(q1.w);
        k0v.x = to_tf32(k0v.x); k0v.y = to_tf32(k0v.y); k0v.z = to_tf32(k0v.z); k0v.w = to_tf32(k0v.w);
        k1v.x = to_tf32(k1v.x); k1v.y = to_tf32(k1v.y); k1v.z = to_tf32(k1v.z); k1v.w = to_tf32(k1v.w);
        v0.x = to_tf32(v0.x); v0.y = to_tf32(v0.y); v0.z = to_tf32(v0.z); v0.w = to_tf32(v0.w);
        v1.x = to_tf32(v1.x); v1.y = to_tf32(v1.y); v1.z = to_tf32(v1.z); v1.w = to_tf32(v1.w);

        // permuted: physical pair (2i, 2i+1) = logical (k_i, k_{i+4})
        float* dq = qs + r * PITCH + p8 * 8;
        float* dk = ks + r * PITCH + p8 * 8;
        reinterpret_cast<float2*>(dq)[0] = make_float2(q0.x, q1.x);
        reinterpret_cast<float2*>(dq)[1] = make_float2(q0.y, q1.y);
        reinterpret_cast<float2*>(dq)[2] = make_float2(q0.z, q1.z);
        reinterpret_cast<float2*>(dq)[3] = make_float2(q0.w, q1.w);
        reinterpret_cast<float2*>(dk)[0] = make_float2(k0v.x, k1v.x);
        reinterpret_cast<float2*>(dk)[1] = make_float2(k0v.y, k1v.y);
        reinterpret_cast<float2*>(dk)[2] = make_float2(k0v.z, k1v.z);
        reinterpret_cast<float2*>(dk)[3] = make_float2(k0v.w, k1v.w);

        float* dv = vs + r * PITCH + p8 * 8;
        reinterpret_cast<float4*>(dv)[0] = v0;
        reinterpret_cast<float4*>(dv)[1] = v1;
    }
    __syncthreads();

    const int wm = w & 7;                // 8 m-groups of 16 rows
    const int wn = w >> 3;               // 4 n-groups
    const int m0 = wm * 16;
    const int lr = lane >> 2;
    const int lc = lane & 3;

    // permuted column indices for ps stores (logical cols 2lc, 2lc+1)
    const int pc0 = (((2 * lc) & 3) << 1) | ((2 * lc) >> 2);
    const int pc1 = (((2 * lc + 1) & 3) << 1) | ((2 * lc + 1) >> 2);

    // ---- Phase C: GEMM1, warp tile 16x32 (4 nb), 8 k-steps, LDS.64 ops ----
    float c1[4][4];
    #pragma unroll
    for (int nb = 0; nb < 4; nb++)
        #pragma unroll
        for (int j = 0; j < 4; j++) c1[nb][j] = 0.0f;

    #pragma unroll
    for (int kk = 0; kk < 8; kk++) {
        const int k0 = kk * 8;
        float2 aA = *reinterpret_cast<const float2*>(&qs[(m0 + lr)     * PITCH + k0 + 2 * lc]); // (a0,a2)
        float2 aB = *reinterpret_cast<const float2*>(&qs[(m0 + lr + 8) * PITCH + k0 + 2 * lc]); // (a1,a3)
        unsigned a0 = __float_as_uint(aA.x), a2 = __float_as_uint(aA.y);
        unsigned a1 = __float_as_uint(aB.x), a3 = __float_as_uint(aB.y);
        #pragma unroll
        for (int nb = 0; nb < 4; nb++) {
            const int n0 = wn * 32 + nb * 8;
            float2 bb = *reinterpret_cast<const float2*>(&ks[(n0 + lr) * PITCH + k0 + 2 * lc]); // (b0,b1)
            mma_tf32(c1[nb], a0, a1, a2, a3,
                     __float_as_uint(bb.x), __float_as_uint(bb.y));
        }
    }
    __syncthreads();   // all warps done reading qs/ks before ps overwrite

    // store scaled scores at PERMUTED column positions (GEMM2's k layout)
    #pragma unroll
    for (int nb = 0; nb < 4; nb++) {
        const int cb = wn * 32 + nb * 8;   // 8-block base
        ps[(m0 + lr)     * PPITCH + cb + pc0] = c1[nb][0] * 0.125f;
        ps[(m0 + lr)     * PPITCH + cb + pc1] = c1[nb][1] * 0.125f;
        ps[(m0 + lr + 8) * PPITCH + cb + pc0] = c1[nb][2] * 0.125f;
        ps[(m0 + lr + 8) * PPITCH + cb + pc1] = c1[nb][3] * 0.125f;
    }
    __syncthreads();

    // ---- Phase D: row softmax (order-invariant under the permutation) ----
    #pragma unroll
    for (int rr = 0; rr < 4; rr++) {
        int r = w * 4 + rr;
        float* row = ps + r * PPITCH;
        float x[4];
        float mx = -1e30f;
        #pragma unroll
        for (int c = 0; c < 4; c++) { x[c] = row[lane + 32 * c]; mx = fmaxf(mx, x[c]); }
        #pragma unroll
        for (int o = 16; o; o >>= 1) mx = fmaxf(mx, __shfl_xor_sync(0xFFFFFFFFu, mx, o));
        float ssum = 0.0f;
        #pragma unroll
        for (int c = 0; c < 4; c++) { x[c] = __expf(x[c] - mx); ssum += x[c]; }
        #pragma unroll
        for (int o = 16; o; o >>= 1) ssum += __shfl_xor_sync(0xFFFFFFFFu, ssum, o);
        float inv = 1.0f / ssum;
        #pragma unroll
        for (int c = 0; c < 4; c++) row[lane + 32 * c] = to_tf32(x[c] * inv);
    }
    __syncthreads();

    // ---- Phase E: GEMM2, warp tile 16x16 (2 nb), 16 k-steps + scatter ----
    float c2[2][4];
    #pragma unroll
    for (int nb = 0; nb < 2; nb++)
        #pragma unroll
        for (int j = 0; j < 4; j++) c2[nb][j] = 0.0f;

    #pragma unroll
    for (int kk = 0; kk < 16; kk++) {
        const int k0 = kk * 8;
        float2 aA = *reinterpret_cast<const float2*>(&ps[(m0 + lr)     * PPITCH + k0 + 2 * lc]); // (a0,a2)
        float2 aB = *reinterpret_cast<const float2*>(&ps[(m0 + lr + 8) * PPITCH + k0 + 2 * lc]); // (a1,a3)
        unsigned a0 = __float_as_uint(aA.x), a2 = __float_as_uint(aA.y);
        unsigned a1 = __float_as_uint(aB.x), a3 = __float_as_uint(aB.y);
        #pragma unroll
        for (int nb = 0; nb < 2; nb++) {
            const int n0 = wn * 16 + nb * 8;
            unsigned b0 = __float_as_uint(vs[(k0 + lc)     * PITCH + n0 + lr]);
            unsigned b1 = __float_as_uint(vs[(k0 + lc + 4) * PITCH + n0 + lr]);
            mma_tf32(c2[nb], a0, a1, a2, a3, b0, b1);
        }
    }

    {
        int r0g = sidx[m0 + lr];
        int r1g = sidx[m0 + lr + 8];
        float* o0 = out + base + (size_t)r0g * D;
        float* o1 = out + base + (size_t)r1g * D;
        #pragma unroll
        for (int nb = 0; nb < 2; nb++) {
            const int d0 = wn * 16 + nb * 8 + lc * 2;
            *reinterpret_cast<float2*>(o0 + d0) = make_float2(c2[nb][0], c2[nb][1]);
            *reinterpret_cast<float2*>(o1 + d0) = make_float2(c2[nb][2], c2[nb][3]);
        }
    }
}

// ---------------------------------------------------------------------------
extern "C" void kernel_launch(void* const* d_in, const int* in_sizes, int n_in,
                              void* d_out, int out_size) {
    const float* q = (const float*)d_in[0];
    const float* k = (const float*)d_in[1];
    const float* v = (const float*)d_in[2];
    float* out = (float*)d_out;

    static void* hist_ptr = nullptr;
    if (hist_ptr == nullptr) cudaGetSymbolAddress(&hist_ptr, g_hist);

    const int fused_smem = (3 * 128 * PITCH) * (int)sizeof(float);
    cudaFuncSetAttribute(fused_kernel, cudaFuncAttributeMaxDynamicSharedMemorySize,
                         fused_smem);

    // reset per-head histograms (tiny; graph-capturable)
    cudaMemsetAsync(hist_ptr, 0, BH * 256 * sizeof(int), 0);

    // 1) importance keys + full output zero + top-byte histograms
    imp_zero_kernel<<<(BH * S) / 128, 256>>>(q, out);

    // 2) fused select + tensor-core attention; overwrites selected rows
    fused_kernel<<<BH, 1024, fused_smem>>>(q, k, v, out);
}